// round 1
// baseline (speedup 1.0000x reference)
#include <cuda_runtime.h>
#include <cuda_bf16.h>

#define NN_MAX 100000
#define NE_MAX 1600000
#define D 128
#define MAXG 4096

// ---------------- scratch (static device globals; no allocs) ----------------
__device__ float g_h[NN_MAX * D];
__device__ float g_agg[NN_MAX * D];
__device__ int   g_degi[NN_MAX];
__device__ int   g_off[NN_MAX + 1];
__device__ int   g_cur[NN_MAX];
__device__ int   g_esrc[NE_MAX];
__device__ float g_hg[MAXG * D];
__device__ float g_cnt[MAXG];
__device__ int   g_part[1024];

// ---------------- degree count ----------------
__global__ void k_deg(const int* __restrict__ dst, int ne) {
    int i = blockIdx.x * blockDim.x + threadIdx.x;
    if (i < ne) atomicAdd(&g_degi[dst[i]], 1);
}

// ---------------- 3-kernel exclusive scan of degrees -> CSR offsets --------
__global__ void k_scan1(int n) {
    __shared__ int sh[1024];
    int t = threadIdx.x, gid = blockIdx.x * 1024 + t;
    int v = (gid < n) ? g_degi[gid] : 0;
    sh[t] = v;
    __syncthreads();
    for (int s = 1; s < 1024; s <<= 1) {
        int u = (t >= s) ? sh[t - s] : 0;
        __syncthreads();
        sh[t] += u;
        __syncthreads();
    }
    if (gid < n) g_off[gid] = sh[t] - v;  // exclusive within block
    if (t == 1023) g_part[blockIdx.x] = sh[1023];
}

__global__ void k_scan2(int nb) {
    __shared__ int sh[1024];
    int t = threadIdx.x;
    int v = (t < nb) ? g_part[t] : 0;
    sh[t] = v;
    __syncthreads();
    for (int s = 1; s < 1024; s <<= 1) {
        int u = (t >= s) ? sh[t - s] : 0;
        __syncthreads();
        sh[t] += u;
        __syncthreads();
    }
    if (t < nb) g_part[t] = sh[t] - v;  // exclusive
}

__global__ void k_scan3(int n, int ne) {
    int gid = blockIdx.x * 1024 + threadIdx.x;
    if (gid < n) g_off[gid] += g_part[blockIdx.x];
    if (gid == 0) g_off[n] = ne;
}

// ---------------- CSR fill (bucket by dst) ----------------
__global__ void k_fill(const int* __restrict__ src, const int* __restrict__ dst, int ne) {
    int i = blockIdx.x * blockDim.x + threadIdx.x;
    if (i < ne) {
        int d = dst[i];
        int p = atomicAdd(&g_cur[d], 1);
        g_esrc[g_off[d] + p] = src[i];
    }
}

// ---------------- h0 = [deg, feat] ----------------
__global__ void k_h0(const float* __restrict__ feat, int n) {
    int idx = blockIdx.x * blockDim.x + threadIdx.x;
    if (idx >= n * D) return;
    int d = idx & (D - 1);
    int node = idx >> 7;
    g_h[idx] = (d == 0) ? (float)g_degi[node] : feat[node * (D - 1) + d - 1];
}

// ---------------- aggregation: warp per node, CSR gather, mean ----------------
__global__ void k_agg(int n) {
    int warp = (blockIdx.x * blockDim.x + threadIdx.x) >> 5;
    int lane = threadIdx.x & 31;
    if (warp >= n) return;
    int e0 = g_off[warp], e1 = g_off[warp + 1];
    const float4* H = (const float4*)g_h;
    float4 a0 = make_float4(0.f, 0.f, 0.f, 0.f);
    float4 a1 = make_float4(0.f, 0.f, 0.f, 0.f);
    float4 a2 = make_float4(0.f, 0.f, 0.f, 0.f);
    float4 a3 = make_float4(0.f, 0.f, 0.f, 0.f);
    int e = e0;
    for (; e + 3 < e1; e += 4) {
        int s0 = g_esrc[e], s1 = g_esrc[e + 1], s2 = g_esrc[e + 2], s3 = g_esrc[e + 3];
        float4 v0 = H[s0 * 32 + lane];
        float4 v1 = H[s1 * 32 + lane];
        float4 v2 = H[s2 * 32 + lane];
        float4 v3 = H[s3 * 32 + lane];
        a0.x += v0.x; a0.y += v0.y; a0.z += v0.z; a0.w += v0.w;
        a1.x += v1.x; a1.y += v1.y; a1.z += v1.z; a1.w += v1.w;
        a2.x += v2.x; a2.y += v2.y; a2.z += v2.z; a2.w += v2.w;
        a3.x += v3.x; a3.y += v3.y; a3.z += v3.z; a3.w += v3.w;
    }
    for (; e < e1; e++) {
        int s = g_esrc[e];
        float4 v = H[s * 32 + lane];
        a0.x += v.x; a0.y += v.y; a0.z += v.z; a0.w += v.w;
    }
    int cnt = e1 - e0;
    float4 out;
    if (cnt > 0) {
        float inv = 1.0f / (float)cnt;
        out.x = (a0.x + a1.x + a2.x + a3.x) * inv;
        out.y = (a0.y + a1.y + a2.y + a3.y) * inv;
        out.z = (a0.z + a1.z + a2.z + a3.z) * inv;
        out.w = (a0.w + a1.w + a2.w + a3.w) * inv;
    } else {
        out = H[warp * 32 + lane];  // zero in-degree keeps old h
    }
    ((float4*)g_agg)[warp * 32 + lane] = out;
}

// ---------------- GEMM: out = relu(A @ W^T + b), A:[n,128], W:[128,128] ------
__global__ __launch_bounds__(256) void k_gemm(const float* __restrict__ A,
                                              const float* __restrict__ W,
                                              const float* __restrict__ b,
                                              float* __restrict__ out,
                                              int n, int do_relu) {
    extern __shared__ float smem[];
    float* Ws = smem;            // [128][128] transposed: Ws[k*128+col]
    float* As = smem + 16384;    // [64][128]
    int tid = threadIdx.x;

    for (int i = tid; i < 16384; i += 256) {
        int col = i >> 7, k = i & 127;
        Ws[k * 128 + col] = W[i];
    }
    int row0 = blockIdx.x * 64;
    for (int i = tid; i < 8192; i += 256) {
        int r = row0 + (i >> 7);
        As[i] = (r < n) ? A[r * 128 + (i & 127)] : 0.f;
    }
    __syncthreads();

    int cx = tid & 31;   // col lane
    int ry = tid >> 5;   // row group 0..7 (same across a warp)
    float acc[8][4];
#pragma unroll
    for (int i = 0; i < 8; i++)
#pragma unroll
        for (int j = 0; j < 4; j++) acc[i][j] = 0.f;

#pragma unroll 4
    for (int k = 0; k < 128; k++) {
        float w0 = Ws[k * 128 + cx];
        float w1 = Ws[k * 128 + cx + 32];
        float w2 = Ws[k * 128 + cx + 64];
        float w3 = Ws[k * 128 + cx + 96];
#pragma unroll
        for (int i = 0; i < 8; i++) {
            float a = As[(ry * 8 + i) * 128 + k];  // warp-broadcast
            acc[i][0] += a * w0;
            acc[i][1] += a * w1;
            acc[i][2] += a * w2;
            acc[i][3] += a * w3;
        }
    }

#pragma unroll
    for (int i = 0; i < 8; i++) {
        int r = row0 + ry * 8 + i;
        if (r >= n) continue;
#pragma unroll
        for (int j = 0; j < 4; j++) {
            int c = cx + 32 * j;
            float v = acc[i][j] + b[c];
            if (do_relu) v = fmaxf(v, 0.f);
            out[r * 128 + c] = v;
        }
    }
}

// ---------------- graph pooling (graph_ids sorted): run-accumulate ----------
__global__ void k_pool(const int* __restrict__ gids, int n) {
    int d = threadIdx.x;  // 128 threads
    int start = blockIdx.x * 128;
    if (start >= n) return;
    int end = min(start + 128, n);
    float acc = 0.f, c = 0.f;
    int g = gids[start];
    for (int i = start; i < end; i++) {
        int gi = gids[i];
        if (gi != g) {
            atomicAdd(&g_hg[g * D + d], acc);
            if (d == 0) atomicAdd(&g_cnt[g], c);
            acc = 0.f; c = 0.f; g = gi;
        }
        acc += g_h[i * D + d];
        c += 1.f;
    }
    atomicAdd(&g_hg[g * D + d], acc);
    if (d == 0) atomicAdd(&g_cnt[g], c);
}

// ---------------- classifier head: (Wc1,bc1) twice (no act), then Wc2 -------
__global__ void k_cls(const float* __restrict__ Wc1, const float* __restrict__ bc1,
                      const float* __restrict__ Wc2, const float* __restrict__ bc2,
                      float* __restrict__ out) {
    __shared__ float x[128];
    __shared__ float t[128];
    __shared__ float red[128];
    int g = blockIdx.x, d = threadIdx.x;
    float c = fmaxf(g_cnt[g], 1.f);
    x[d] = g_hg[g * D + d] / c;
    __syncthreads();
    float a = bc1[d];
    for (int k = 0; k < 128; k++) a += Wc1[d * 128 + k] * x[k];
    t[d] = a;
    __syncthreads();
    float a2 = bc1[d];
    for (int k = 0; k < 128; k++) a2 += Wc1[d * 128 + k] * t[k];
    x[d] = a2;
    __syncthreads();
    red[d] = Wc2[d] * x[d];
    __syncthreads();
    for (int s = 64; s > 0; s >>= 1) {
        if (d < s) red[d] += red[d + s];
        __syncthreads();
    }
    if (d == 0) out[g] = red[0] + bc2[0];
}

// ---------------- launch ----------------
extern "C" void kernel_launch(void* const* d_in, const int* in_sizes, int n_in,
                              void* d_out, int out_size) {
    const float* feat = (const float*)d_in[0];
    const int*   src  = (const int*)d_in[1];
    const int*   dst  = (const int*)d_in[2];
    const int*   gids = (const int*)d_in[3];
    int base = (n_in == 15) ? 5 : 4;  // num_graphs may or may not be a tensor input
    const float* W0  = (const float*)d_in[base + 0];
    const float* b0  = (const float*)d_in[base + 1];
    const float* W1  = (const float*)d_in[base + 2];
    const float* b1  = (const float*)d_in[base + 3];
    const float* W2  = (const float*)d_in[base + 4];
    const float* b2  = (const float*)d_in[base + 5];
    const float* Wc1 = (const float*)d_in[base + 6];
    const float* bc1 = (const float*)d_in[base + 7];
    const float* Wc2 = (const float*)d_in[base + 8];
    const float* bc2 = (const float*)d_in[base + 9];
    float* out = (float*)d_out;

    int nn = in_sizes[0] / (D - 1);
    int ne = in_sizes[1];
    int ng = out_size;

    // symbol addresses for memset
    void *p_degi, *p_cur, *p_hg, *p_cnt;
    cudaGetSymbolAddress(&p_degi, g_degi);
    cudaGetSymbolAddress(&p_cur, g_cur);
    cudaGetSymbolAddress(&p_hg, g_hg);
    cudaGetSymbolAddress(&p_cnt, g_cnt);
    cudaMemsetAsync(p_degi, 0, nn * sizeof(int));
    cudaMemsetAsync(p_cur, 0, nn * sizeof(int));
    cudaMemsetAsync(p_hg, 0, (size_t)ng * D * sizeof(float));
    cudaMemsetAsync(p_cnt, 0, ng * sizeof(float));

    // degrees
    k_deg<<<(ne + 255) / 256, 256>>>(dst, ne);

    // scan -> CSR offsets
    int nb = (nn + 1023) / 1024;
    k_scan1<<<nb, 1024>>>(nn);
    k_scan2<<<1, 1024>>>(nb);
    k_scan3<<<nb, 1024>>>(nn, ne);

    // CSR fill
    k_fill<<<(ne + 255) / 256, 256>>>(src, dst, ne);

    // h0
    k_h0<<<(nn * D + 255) / 256, 256>>>(feat, nn);

    // layers
    float *h, *agg;
    cudaGetSymbolAddress((void**)&h, g_h);
    cudaGetSymbolAddress((void**)&agg, g_agg);

    const size_t smem_gemm = (16384 + 8192) * sizeof(float);
    cudaFuncSetAttribute(k_gemm, cudaFuncAttributeMaxDynamicSharedMemorySize, (int)smem_gemm);

    int agg_grid = (nn * 32 + 255) / 256;
    int gemm_grid = (nn + 63) / 64;

    const float* Ws[3] = {W0, W1, W2};
    const float* bs[3] = {b0, b1, b2};
    for (int l = 0; l < 3; l++) {
        k_agg<<<agg_grid, 256>>>(nn);
        k_gemm<<<gemm_grid, 256, smem_gemm>>>(agg, Ws[l], bs[l], h, nn, 1);
    }

    // pooling
    k_pool<<<(nn + 127) / 128, 128>>>(gids, nn);

    // classifier head
    k_cls<<<ng, 128>>>(Wc1, bc1, Wc2, bc2, out);
}

// round 2
// speedup vs baseline: 1.8053x; 1.8053x over previous
#include <cuda_runtime.h>
#include <cuda_bf16.h>

#define NN_MAX 100000
#define NE_MAX 1600000
#define D 128
#define MAXG 4096

// ---------------- scratch (static device globals; no allocs) ----------------
__device__ float g_h[NN_MAX * D];
__device__ float g_agg[NN_MAX * D];
__device__ int   g_degi[NN_MAX];
__device__ int   g_off[NN_MAX + 1];
__device__ int   g_cur[NN_MAX];
__device__ int   g_esrc[NE_MAX];
__device__ float g_hg[MAXG * D];
__device__ float g_cnt[MAXG];
__device__ int   g_part[1024];

// ---------------- degree count ----------------
__global__ void k_deg(const int* __restrict__ dst, int ne) {
    int i = blockIdx.x * blockDim.x + threadIdx.x;
    if (i < ne) atomicAdd(&g_degi[dst[i]], 1);
}

// ---------------- 3-kernel exclusive scan of degrees -> CSR offsets --------
__global__ void k_scan1(int n) {
    __shared__ int sh[1024];
    int t = threadIdx.x, gid = blockIdx.x * 1024 + t;
    int v = (gid < n) ? g_degi[gid] : 0;
    sh[t] = v;
    __syncthreads();
    for (int s = 1; s < 1024; s <<= 1) {
        int u = (t >= s) ? sh[t - s] : 0;
        __syncthreads();
        sh[t] += u;
        __syncthreads();
    }
    if (gid < n) g_off[gid] = sh[t] - v;  // exclusive within block
    if (t == 1023) g_part[blockIdx.x] = sh[1023];
}

__global__ void k_scan2(int nb) {
    __shared__ int sh[1024];
    int t = threadIdx.x;
    int v = (t < nb) ? g_part[t] : 0;
    sh[t] = v;
    __syncthreads();
    for (int s = 1; s < 1024; s <<= 1) {
        int u = (t >= s) ? sh[t - s] : 0;
        __syncthreads();
        sh[t] += u;
        __syncthreads();
    }
    if (t < nb) g_part[t] = sh[t] - v;  // exclusive
}

__global__ void k_scan3(int n, int ne) {
    int gid = blockIdx.x * 1024 + threadIdx.x;
    if (gid < n) g_off[gid] += g_part[blockIdx.x];
    if (gid == 0) g_off[n] = ne;
}

// ---------------- CSR fill (bucket by dst) ----------------
__global__ void k_fill(const int* __restrict__ src, const int* __restrict__ dst, int ne) {
    int i = blockIdx.x * blockDim.x + threadIdx.x;
    if (i < ne) {
        int d = dst[i];
        int p = atomicAdd(&g_cur[d], 1);
        g_esrc[g_off[d] + p] = src[i];
    }
}

// ---------------- h0 = [deg, feat] ----------------
__global__ void k_h0(const float* __restrict__ feat, int n) {
    int idx = blockIdx.x * blockDim.x + threadIdx.x;
    if (idx >= n * D) return;
    int d = idx & (D - 1);
    int node = idx >> 7;
    g_h[idx] = (d == 0) ? (float)g_degi[node] : feat[node * (D - 1) + d - 1];
}

// ---------------- aggregation: warp per node, CSR gather, mean ----------------
__global__ void k_agg(int n) {
    int warp = (blockIdx.x * blockDim.x + threadIdx.x) >> 5;
    int lane = threadIdx.x & 31;
    if (warp >= n) return;
    int e0 = g_off[warp], e1 = g_off[warp + 1];
    const float4* H = (const float4*)g_h;
    float4 a0 = make_float4(0.f, 0.f, 0.f, 0.f);
    float4 a1 = make_float4(0.f, 0.f, 0.f, 0.f);
    float4 a2 = make_float4(0.f, 0.f, 0.f, 0.f);
    float4 a3 = make_float4(0.f, 0.f, 0.f, 0.f);
    int e = e0;
    for (; e + 3 < e1; e += 4) {
        int s0 = g_esrc[e], s1 = g_esrc[e + 1], s2 = g_esrc[e + 2], s3 = g_esrc[e + 3];
        float4 v0 = H[s0 * 32 + lane];
        float4 v1 = H[s1 * 32 + lane];
        float4 v2 = H[s2 * 32 + lane];
        float4 v3 = H[s3 * 32 + lane];
        a0.x += v0.x; a0.y += v0.y; a0.z += v0.z; a0.w += v0.w;
        a1.x += v1.x; a1.y += v1.y; a1.z += v1.z; a1.w += v1.w;
        a2.x += v2.x; a2.y += v2.y; a2.z += v2.z; a2.w += v2.w;
        a3.x += v3.x; a3.y += v3.y; a3.z += v3.z; a3.w += v3.w;
    }
    for (; e < e1; e++) {
        int s = g_esrc[e];
        float4 v = H[s * 32 + lane];
        a0.x += v.x; a0.y += v.y; a0.z += v.z; a0.w += v.w;
    }
    int cnt = e1 - e0;
    float4 out;
    if (cnt > 0) {
        float inv = 1.0f / (float)cnt;
        out.x = (a0.x + a1.x + a2.x + a3.x) * inv;
        out.y = (a0.y + a1.y + a2.y + a3.y) * inv;
        out.z = (a0.z + a1.z + a2.z + a3.z) * inv;
        out.w = (a0.w + a1.w + a2.w + a3.w) * inv;
    } else {
        out = H[warp * 32 + lane];  // zero in-degree keeps old h
    }
    ((float4*)g_agg)[warp * 32 + lane] = out;
}

// ---------------- tensor-core GEMM: out = relu(A @ W^T + b) ------------------
// A:[n,128] fp32, W:[128,128] fp32 (row-major, out_c = row). tf32 mma m16n8k8.
// CTA = 8 warps, each warp computes a 16x128 output tile. W^T staged in smem
// (pre-converted to tf32, padded stride 132 => conflict-free). A fragments
// loaded directly from gmem (each element read exactly once; L2-resident).
#define WT_STRIDE 132

__device__ __forceinline__ unsigned f2tf32(float f) {
    unsigned u;
    asm("cvt.rna.tf32.f32 %0, %1;" : "=r"(u) : "f"(f));
    return u;
}

__global__ __launch_bounds__(256, 2) void k_gemm_tc(const float* __restrict__ A,
                                                    const float* __restrict__ W,
                                                    const float* __restrict__ bias,
                                                    float* __restrict__ out,
                                                    int n) {
    extern __shared__ unsigned smem_u[];  // Wt[k][c] (tf32 bits), k=0..127, c=0..127, stride 132
    int tid = threadIdx.x;

    // stage W^T, converted to tf32 bits
    for (int i = tid; i < 16384; i += 256) {
        int c = i >> 7, k = i & 127;
        smem_u[k * WT_STRIDE + c] = f2tf32(W[i]);
    }
    __syncthreads();

    int warp = tid >> 5, lane = tid & 31;
    int g = lane >> 2;        // 0..7
    int t4 = lane & 3;        // 0..3
    int row0 = blockIdx.x * 128 + warp * 16;
    int r1 = row0 + g;
    int r2 = row0 + g + 8;
    const float* a1p = A + (size_t)min(r1, n - 1) * 128;
    const float* a2p = A + (size_t)min(r2, n - 1) * 128;

    float acc[16][4];
#pragma unroll
    for (int i = 0; i < 16; i++) {
        acc[i][0] = 0.f; acc[i][1] = 0.f; acc[i][2] = 0.f; acc[i][3] = 0.f;
    }

#pragma unroll
    for (int k0 = 0; k0 < 128; k0 += 8) {
        unsigned a0 = f2tf32(a1p[k0 + t4]);
        unsigned a1 = f2tf32(a2p[k0 + t4]);
        unsigned a2 = f2tf32(a1p[k0 + 4 + t4]);
        unsigned a3 = f2tf32(a2p[k0 + 4 + t4]);
        const unsigned* w0 = smem_u + (k0 + t4) * WT_STRIDE + g;
        const unsigned* w1 = smem_u + (k0 + 4 + t4) * WT_STRIDE + g;
#pragma unroll
        for (int nt = 0; nt < 16; nt++) {
            unsigned b0 = w0[nt * 8];
            unsigned b1 = w1[nt * 8];
            asm volatile(
                "mma.sync.aligned.m16n8k8.row.col.f32.tf32.tf32.f32 "
                "{%0,%1,%2,%3}, {%4,%5,%6,%7}, {%8,%9}, {%0,%1,%2,%3};"
                : "+f"(acc[nt][0]), "+f"(acc[nt][1]), "+f"(acc[nt][2]), "+f"(acc[nt][3])
                : "r"(a0), "r"(a1), "r"(a2), "r"(a3), "r"(b0), "r"(b1));
        }
    }

    // epilogue: bias + relu + store (float2 per reg-pair)
    bool ok1 = r1 < n, ok2 = r2 < n;
#pragma unroll
    for (int nt = 0; nt < 16; nt++) {
        int col = nt * 8 + t4 * 2;
        float2 bb = *(const float2*)&bias[col];
        if (ok1) {
            float2 v;
            v.x = fmaxf(acc[nt][0] + bb.x, 0.f);
            v.y = fmaxf(acc[nt][1] + bb.y, 0.f);
            *(float2*)&out[(size_t)r1 * 128 + col] = v;
        }
        if (ok2) {
            float2 v;
            v.x = fmaxf(acc[nt][2] + bb.x, 0.f);
            v.y = fmaxf(acc[nt][3] + bb.y, 0.f);
            *(float2*)&out[(size_t)r2 * 128 + col] = v;
        }
    }
}

// ---------------- graph pooling (graph_ids sorted): run-accumulate ----------
__global__ void k_pool(const int* __restrict__ gids, int n) {
    int d = threadIdx.x;  // 128 threads
    int start = blockIdx.x * 128;
    if (start >= n) return;
    int end = min(start + 128, n);
    float acc = 0.f, c = 0.f;
    int g = gids[start];
    for (int i = start; i < end; i++) {
        int gi = gids[i];
        if (gi != g) {
            atomicAdd(&g_hg[g * D + d], acc);
            if (d == 0) atomicAdd(&g_cnt[g], c);
            acc = 0.f; c = 0.f; g = gi;
        }
        acc += g_h[i * D + d];
        c += 1.f;
    }
    atomicAdd(&g_hg[g * D + d], acc);
    if (d == 0) atomicAdd(&g_cnt[g], c);
}

// ---------------- classifier head: (Wc1,bc1) twice (no act), then Wc2 -------
__global__ void k_cls(const float* __restrict__ Wc1, const float* __restrict__ bc1,
                      const float* __restrict__ Wc2, const float* __restrict__ bc2,
                      float* __restrict__ out) {
    __shared__ float x[128];
    __shared__ float t[128];
    __shared__ float red[128];
    int g = blockIdx.x, d = threadIdx.x;
    float c = fmaxf(g_cnt[g], 1.f);
    x[d] = g_hg[g * D + d] / c;
    __syncthreads();
    float a = bc1[d];
    for (int k = 0; k < 128; k++) a += Wc1[d * 128 + k] * x[k];
    t[d] = a;
    __syncthreads();
    float a2 = bc1[d];
    for (int k = 0; k < 128; k++) a2 += Wc1[d * 128 + k] * t[k];
    x[d] = a2;
    __syncthreads();
    red[d] = Wc2[d] * x[d];
    __syncthreads();
    for (int s = 64; s > 0; s >>= 1) {
        if (d < s) red[d] += red[d + s];
        __syncthreads();
    }
    if (d == 0) out[g] = red[0] + bc2[0];
}

// ---------------- launch ----------------
extern "C" void kernel_launch(void* const* d_in, const int* in_sizes, int n_in,
                              void* d_out, int out_size) {
    const float* feat = (const float*)d_in[0];
    const int*   src  = (const int*)d_in[1];
    const int*   dst  = (const int*)d_in[2];
    const int*   gids = (const int*)d_in[3];
    int base = (n_in == 15) ? 5 : 4;  // num_graphs may or may not be a tensor input
    const float* W0  = (const float*)d_in[base + 0];
    const float* b0  = (const float*)d_in[base + 1];
    const float* W1  = (const float*)d_in[base + 2];
    const float* b1  = (const float*)d_in[base + 3];
    const float* W2  = (const float*)d_in[base + 4];
    const float* b2  = (const float*)d_in[base + 5];
    const float* Wc1 = (const float*)d_in[base + 6];
    const float* bc1 = (const float*)d_in[base + 7];
    const float* Wc2 = (const float*)d_in[base + 8];
    const float* bc2 = (const float*)d_in[base + 9];
    float* out = (float*)d_out;

    int nn = in_sizes[0] / (D - 1);
    int ne = in_sizes[1];
    int ng = out_size;

    // symbol addresses for memset
    void *p_degi, *p_cur, *p_hg, *p_cnt;
    cudaGetSymbolAddress(&p_degi, g_degi);
    cudaGetSymbolAddress(&p_cur, g_cur);
    cudaGetSymbolAddress(&p_hg, g_hg);
    cudaGetSymbolAddress(&p_cnt, g_cnt);
    cudaMemsetAsync(p_degi, 0, nn * sizeof(int));
    cudaMemsetAsync(p_cur, 0, nn * sizeof(int));
    cudaMemsetAsync(p_hg, 0, (size_t)ng * D * sizeof(float));
    cudaMemsetAsync(p_cnt, 0, ng * sizeof(float));

    // degrees
    k_deg<<<(ne + 255) / 256, 256>>>(dst, ne);

    // scan -> CSR offsets
    int nb = (nn + 1023) / 1024;
    k_scan1<<<nb, 1024>>>(nn);
    k_scan2<<<1, 1024>>>(nb);
    k_scan3<<<nb, 1024>>>(nn, ne);

    // CSR fill
    k_fill<<<(ne + 255) / 256, 256>>>(src, dst, ne);

    // h0
    k_h0<<<(nn * D + 255) / 256, 256>>>(feat, nn);

    // layers
    float *h, *agg;
    cudaGetSymbolAddress((void**)&h, g_h);
    cudaGetSymbolAddress((void**)&agg, g_agg);

    const size_t smem_gemm = 128 * WT_STRIDE * sizeof(unsigned);  // 67584
    cudaFuncSetAttribute(k_gemm_tc, cudaFuncAttributeMaxDynamicSharedMemorySize, (int)smem_gemm);

    int agg_grid = (nn * 32 + 255) / 256;
    int gemm_grid = (nn + 127) / 128;

    const float* Ws[3] = {W0, W1, W2};
    const float* bs[3] = {b0, b1, b2};
    for (int l = 0; l < 3; l++) {
        k_agg<<<agg_grid, 256>>>(nn);
        k_gemm_tc<<<gemm_grid, 256, smem_gemm>>>(agg, Ws[l], bs[l], h, nn);
    }

    // pooling
    k_pool<<<(nn + 127) / 128, 128>>>(gids, nn);

    // classifier head
    k_cls<<<ng, 128>>>(Wc1, bc1, Wc2, bc2, out);
}

// round 3
// speedup vs baseline: 2.6113x; 1.4464x over previous
#include <cuda_runtime.h>
#include <cuda_fp16.h>

#define NN_MAX 100000
#define NE_MAX 1600000
#define D 128
#define MAXG 4096

// ---------------- scratch (static device globals; no allocs) ----------------
__device__ __align__(16) __half g_h[NN_MAX * D];
__device__ __align__(16) __half g_agg[NN_MAX * D];
__device__ __align__(16) __half g_Wh[3 * D * D];
__device__ int   g_degi[NN_MAX];
__device__ int   g_off[NN_MAX + 1];
__device__ int   g_cur[NN_MAX];
__device__ int   g_esrc[NE_MAX];
__device__ float g_hg[MAXG * D];
__device__ float g_cnt[MAXG];
__device__ int   g_part[1024];

// ---------------- degree count ----------------
__global__ void k_deg(const int* __restrict__ dst, int ne) {
    int i = blockIdx.x * blockDim.x + threadIdx.x;
    if (i < ne) atomicAdd(&g_degi[dst[i]], 1);
}

// ---------------- 3-kernel exclusive scan of degrees -> CSR offsets --------
__global__ void k_scan1(int n) {
    __shared__ int sh[1024];
    int t = threadIdx.x, gid = blockIdx.x * 1024 + t;
    int v = (gid < n) ? g_degi[gid] : 0;
    sh[t] = v;
    __syncthreads();
    for (int s = 1; s < 1024; s <<= 1) {
        int u = (t >= s) ? sh[t - s] : 0;
        __syncthreads();
        sh[t] += u;
        __syncthreads();
    }
    if (gid < n) g_off[gid] = sh[t] - v;
    if (t == 1023) g_part[blockIdx.x] = sh[1023];
}

__global__ void k_scan2(int nb) {
    __shared__ int sh[1024];
    int t = threadIdx.x;
    int v = (t < nb) ? g_part[t] : 0;
    sh[t] = v;
    __syncthreads();
    for (int s = 1; s < 1024; s <<= 1) {
        int u = (t >= s) ? sh[t - s] : 0;
        __syncthreads();
        sh[t] += u;
        __syncthreads();
    }
    if (t < nb) g_part[t] = sh[t] - v;
}

__global__ void k_scan3(int n, int ne) {
    int gid = blockIdx.x * 1024 + threadIdx.x;
    if (gid < n) g_off[gid] += g_part[blockIdx.x];
    if (gid == 0) g_off[n] = ne;
}

// ---------------- CSR fill (bucket by dst) ----------------
__global__ void k_fill(const int* __restrict__ src, const int* __restrict__ dst, int ne) {
    int i = blockIdx.x * blockDim.x + threadIdx.x;
    if (i < ne) {
        int d = dst[i];
        int p = atomicAdd(&g_cur[d], 1);
        g_esrc[g_off[d] + p] = src[i];
    }
}

// ---------------- h0 = [deg, feat] (fp16) ----------------
__global__ void k_h0(const float* __restrict__ feat, int n) {
    int idx = blockIdx.x * blockDim.x + threadIdx.x;
    if (idx >= n * D) return;
    int d = idx & (D - 1);
    int node = idx >> 7;
    float v = (d == 0) ? (float)g_degi[node] : feat[node * (D - 1) + d - 1];
    g_h[idx] = __float2half(v);
}

// ---------------- W -> fp16 (once per launch) ----------------
__global__ void k_wconv(const float* __restrict__ W0, const float* __restrict__ W1,
                        const float* __restrict__ W2) {
    int i = blockIdx.x * blockDim.x + threadIdx.x;
    if (i >= D * D) return;
    g_Wh[i] = __float2half(W0[i]);
    g_Wh[D * D + i] = __float2half(W1[i]);
    g_Wh[2 * D * D + i] = __float2half(W2[i]);
}

// ---------------- aggregation: warp per node, fp16 gather, fp32 accum --------
__global__ void k_agg(int n) {
    int warp = (blockIdx.x * blockDim.x + threadIdx.x) >> 5;
    int lane = threadIdx.x & 31;
    if (warp >= n) return;
    int e0 = g_off[warp], e1 = g_off[warp + 1];
    const uint2* H = (const uint2*)g_h;  // row = 32 uint2 (128 halves)
    float4 a0 = make_float4(0.f, 0.f, 0.f, 0.f);
    float4 a1 = make_float4(0.f, 0.f, 0.f, 0.f);
    float4 a2 = make_float4(0.f, 0.f, 0.f, 0.f);
    float4 a3 = make_float4(0.f, 0.f, 0.f, 0.f);
    int e = e0;
    for (; e + 3 < e1; e += 4) {
        int s0 = g_esrc[e], s1 = g_esrc[e + 1], s2 = g_esrc[e + 2], s3 = g_esrc[e + 3];
        uint2 v0 = H[s0 * 32 + lane];
        uint2 v1 = H[s1 * 32 + lane];
        uint2 v2 = H[s2 * 32 + lane];
        uint2 v3 = H[s3 * 32 + lane];
        float2 f;
        f = __half22float2(*(__half2*)&v0.x); a0.x += f.x; a0.y += f.y;
        f = __half22float2(*(__half2*)&v0.y); a0.z += f.x; a0.w += f.y;
        f = __half22float2(*(__half2*)&v1.x); a1.x += f.x; a1.y += f.y;
        f = __half22float2(*(__half2*)&v1.y); a1.z += f.x; a1.w += f.y;
        f = __half22float2(*(__half2*)&v2.x); a2.x += f.x; a2.y += f.y;
        f = __half22float2(*(__half2*)&v2.y); a2.z += f.x; a2.w += f.y;
        f = __half22float2(*(__half2*)&v3.x); a3.x += f.x; a3.y += f.y;
        f = __half22float2(*(__half2*)&v3.y); a3.z += f.x; a3.w += f.y;
    }
    for (; e < e1; e++) {
        int s = g_esrc[e];
        uint2 v = H[s * 32 + lane];
        float2 f;
        f = __half22float2(*(__half2*)&v.x); a0.x += f.x; a0.y += f.y;
        f = __half22float2(*(__half2*)&v.y); a0.z += f.x; a0.w += f.y;
    }
    int cnt = e1 - e0;
    uint2* Ag = (uint2*)g_agg;
    if (cnt > 0) {
        float inv = 1.0f / (float)cnt;
        __half2 lo = __floats2half2_rn((a0.x + a1.x + a2.x + a3.x) * inv,
                                       (a0.y + a1.y + a2.y + a3.y) * inv);
        __half2 hi = __floats2half2_rn((a0.z + a1.z + a2.z + a3.z) * inv,
                                       (a0.w + a1.w + a2.w + a3.w) * inv);
        uint2 o;
        o.x = *(unsigned*)&lo;
        o.y = *(unsigned*)&hi;
        Ag[warp * 32 + lane] = o;
    } else {
        Ag[warp * 32 + lane] = H[warp * 32 + lane];  // zero in-degree keeps old h
    }
}

// ---------------- tensor-core GEMM (fp16 m16n8k16): out = relu(A @ W^T + b) --
// A:[n,128] fp16, Wh:[128,128] fp16 row-major (row = out channel). B is .col
// => B[k][n] = W[n][k], so B fragments read W rows directly (no transpose).
// W staged in smem with stride 136 halves => conflict-free fragment loads.
#define WS_STRIDE 136

__global__ __launch_bounds__(256, 2) void k_gemm_hc(const __half* __restrict__ A,
                                                    const __half* __restrict__ Wh,
                                                    const float* __restrict__ bias,
                                                    __half* __restrict__ out,
                                                    int n) {
    extern __shared__ __half ws[];  // [128][WS_STRIDE]
    int tid = threadIdx.x;

    // stage W (fp16) into padded smem
    const uint4* Wv = (const uint4*)Wh;  // 2048 x 8 halves
    for (int i = tid; i < 2048; i += 256) {
        int nrow = i >> 4;
        int kk = (i & 15) * 8;
        *(uint4*)&ws[nrow * WS_STRIDE + kk] = Wv[i];
    }
    __syncthreads();

    int warp = tid >> 5, lane = tid & 31;
    int g = lane >> 2;    // 0..7
    int t4 = lane & 3;    // 0..3
    int row0 = blockIdx.x * 128 + warp * 16;
    int r1 = row0 + g;
    int r2 = row0 + g + 8;
    const __half* a1p = A + (size_t)min(r1, n - 1) * 128 + 2 * t4;
    const __half* a2p = A + (size_t)min(r2, n - 1) * 128 + 2 * t4;

    float acc[16][4];
#pragma unroll
    for (int i = 0; i < 16; i++) {
        acc[i][0] = 0.f; acc[i][1] = 0.f; acc[i][2] = 0.f; acc[i][3] = 0.f;
    }

#pragma unroll
    for (int k0 = 0; k0 < 128; k0 += 16) {
        unsigned fa0 = *(const unsigned*)(a1p + k0);
        unsigned fa1 = *(const unsigned*)(a2p + k0);
        unsigned fa2 = *(const unsigned*)(a1p + k0 + 8);
        unsigned fa3 = *(const unsigned*)(a2p + k0 + 8);
        const __half* wb = ws + k0 + 2 * t4 + g * WS_STRIDE;
#pragma unroll
        for (int nt = 0; nt < 16; nt++) {
            unsigned b0 = *(const unsigned*)(wb + nt * 8 * WS_STRIDE);
            unsigned b1 = *(const unsigned*)(wb + nt * 8 * WS_STRIDE + 8);
            asm volatile(
                "mma.sync.aligned.m16n8k16.row.col.f32.f16.f16.f32 "
                "{%0,%1,%2,%3}, {%4,%5,%6,%7}, {%8,%9}, {%0,%1,%2,%3};"
                : "+f"(acc[nt][0]), "+f"(acc[nt][1]), "+f"(acc[nt][2]), "+f"(acc[nt][3])
                : "r"(fa0), "r"(fa1), "r"(fa2), "r"(fa3), "r"(b0), "r"(b1));
        }
    }

    bool ok1 = r1 < n, ok2 = r2 < n;
#pragma unroll
    for (int nt = 0; nt < 16; nt++) {
        int col = nt * 8 + 2 * t4;
        float2 bb = *(const float2*)&bias[col];
        if (ok1) {
            __half2 v = __floats2half2_rn(fmaxf(acc[nt][0] + bb.x, 0.f),
                                          fmaxf(acc[nt][1] + bb.y, 0.f));
            *(__half2*)&out[(size_t)r1 * 128 + col] = v;
        }
        if (ok2) {
            __half2 v = __floats2half2_rn(fmaxf(acc[nt][2] + bb.x, 0.f),
                                          fmaxf(acc[nt][3] + bb.y, 0.f));
            *(__half2*)&out[(size_t)r2 * 128 + col] = v;
        }
    }
}

// ---------------- graph pooling (graph_ids sorted): run-accumulate ----------
__global__ void k_pool(const int* __restrict__ gids, int n) {
    int d = threadIdx.x;  // 128 threads
    int start = blockIdx.x * 128;
    if (start >= n) return;
    int end = min(start + 128, n);
    float acc = 0.f, c = 0.f;
    int g = gids[start];
    for (int i = start; i < end; i++) {
        int gi = gids[i];
        if (gi != g) {
            atomicAdd(&g_hg[g * D + d], acc);
            if (d == 0) atomicAdd(&g_cnt[g], c);
            acc = 0.f; c = 0.f; g = gi;
        }
        acc += __half2float(g_h[(size_t)i * D + d]);
        c += 1.f;
    }
    atomicAdd(&g_hg[g * D + d], acc);
    if (d == 0) atomicAdd(&g_cnt[g], c);
}

// ---------------- classifier head: (Wc1,bc1) twice (no act), then Wc2 -------
__global__ void k_cls(const float* __restrict__ Wc1, const float* __restrict__ bc1,
                      const float* __restrict__ Wc2, const float* __restrict__ bc2,
                      float* __restrict__ out) {
    __shared__ float x[128];
    __shared__ float t[128];
    __shared__ float red[128];
    int g = blockIdx.x, d = threadIdx.x;
    float c = fmaxf(g_cnt[g], 1.f);
    x[d] = g_hg[g * D + d] / c;
    __syncthreads();
    float a = bc1[d];
    for (int k = 0; k < 128; k++) a += Wc1[d * 128 + k] * x[k];
    t[d] = a;
    __syncthreads();
    float a2 = bc1[d];
    for (int k = 0; k < 128; k++) a2 += Wc1[d * 128 + k] * t[k];
    x[d] = a2;
    __syncthreads();
    red[d] = Wc2[d] * x[d];
    __syncthreads();
    for (int s = 64; s > 0; s >>= 1) {
        if (d < s) red[d] += red[d + s];
        __syncthreads();
    }
    if (d == 0) out[g] = red[0] + bc2[0];
}

// ---------------- launch ----------------
extern "C" void kernel_launch(void* const* d_in, const int* in_sizes, int n_in,
                              void* d_out, int out_size) {
    const float* feat = (const float*)d_in[0];
    const int*   src  = (const int*)d_in[1];
    const int*   dst  = (const int*)d_in[2];
    const int*   gids = (const int*)d_in[3];
    int base = (n_in == 15) ? 5 : 4;
    const float* W0  = (const float*)d_in[base + 0];
    const float* b0  = (const float*)d_in[base + 1];
    const float* W1  = (const float*)d_in[base + 2];
    const float* b1  = (const float*)d_in[base + 3];
    const float* W2  = (const float*)d_in[base + 4];
    const float* b2  = (const float*)d_in[base + 5];
    const float* Wc1 = (const float*)d_in[base + 6];
    const float* bc1 = (const float*)d_in[base + 7];
    const float* Wc2 = (const float*)d_in[base + 8];
    const float* bc2 = (const float*)d_in[base + 9];
    float* out = (float*)d_out;

    int nn = in_sizes[0] / (D - 1);
    int ne = in_sizes[1];
    int ng = out_size;

    void *p_degi, *p_cur, *p_hg, *p_cnt;
    cudaGetSymbolAddress(&p_degi, g_degi);
    cudaGetSymbolAddress(&p_cur, g_cur);
    cudaGetSymbolAddress(&p_hg, g_hg);
    cudaGetSymbolAddress(&p_cnt, g_cnt);
    cudaMemsetAsync(p_degi, 0, nn * sizeof(int));
    cudaMemsetAsync(p_cur, 0, nn * sizeof(int));
    cudaMemsetAsync(p_hg, 0, (size_t)ng * D * sizeof(float));
    cudaMemsetAsync(p_cnt, 0, ng * sizeof(float));

    // degrees
    k_deg<<<(ne + 255) / 256, 256>>>(dst, ne);

    // scan -> CSR offsets
    int nb = (nn + 1023) / 1024;
    k_scan1<<<nb, 1024>>>(nn);
    k_scan2<<<1, 1024>>>(nb);
    k_scan3<<<nb, 1024>>>(nn, ne);

    // CSR fill
    k_fill<<<(ne + 255) / 256, 256>>>(src, dst, ne);

    // h0 + weight conversion
    k_h0<<<(nn * D + 255) / 256, 256>>>(feat, nn);
    k_wconv<<<(D * D + 255) / 256, 256>>>(W0, W1, W2);

    __half *h, *agg, *wh;
    cudaGetSymbolAddress((void**)&h, g_h);
    cudaGetSymbolAddress((void**)&agg, g_agg);
    cudaGetSymbolAddress((void**)&wh, g_Wh);

    const size_t smem_gemm = 128 * WS_STRIDE * sizeof(__half);  // 34816
    cudaFuncSetAttribute(k_gemm_hc, cudaFuncAttributeMaxDynamicSharedMemorySize, (int)smem_gemm);

    int agg_grid = (nn * 32 + 255) / 256;
    int gemm_grid = (nn + 127) / 128;

    const float* bs[3] = {b0, b1, b2};
    for (int l = 0; l < 3; l++) {
        k_agg<<<agg_grid, 256>>>(nn);
        k_gemm_hc<<<gemm_grid, 256, smem_gemm>>>(agg, wh + l * D * D, bs[l], h, nn);
    }

    // pooling
    k_pool<<<(nn + 127) / 128, 128>>>(gids, nn);

    // classifier head
    k_cls<<<ng, 128>>>(Wc1, bc1, Wc2, bc2, out);
}